// round 17
// baseline (speedup 1.0000x reference)
#include <cuda_runtime.h>
#include <cstdint>

// ---------------------------------------------------------------------------
// SAGEConv (mean agg): out = relu(feat @ W_self + scatter_mean(feat[src]->dst) @ W_neigh + bias)
// N=100000, E=1600000, D_IN=D_OUT=64
//
// CSR-pull pipeline (no feature atomics, graph-capturable, no allocs):
//  K0 zero_cnt : zero per-node edge counters
//  K1 hist     : in-degree histogram (int atomics)
//  K2 scan     : single-block exclusive scan -> row_ptr, cursor
//  K3 fill     : scatter src ids into CSR slots (cursor atomics)
//  K4 pull     : one node per 16-lane group; register accumulation of
//                neighbor rows (coalesced 256B gathers), pre-scaled by 1/deg
//  K5 out_gemm : 256-node x 64-col tile, 8x8 per thread, packed f32x2 FMA
// All scratch is fully overwritten every execution -> replay-deterministic.
// ---------------------------------------------------------------------------

#define D_IN 64
#define D_OUT 64
#define MAX_NODES 100000
#define MAX_EDGES 1600000

__device__ int g_cnt[MAX_NODES];
__device__ int g_rowptr[MAX_NODES + 1];
__device__ int g_cursor[MAX_NODES];
__device__ int g_colidx[MAX_EDGES];
__device__ __align__(16) float g_hneigh[MAX_NODES * D_IN];

// ---------------------------------------------------------------------------
// Index-width detection (int32 vs int64): int32 data misread as int64 pairs
// two random indices -> out-of-range with prob ~1 per sample; 32-64 samples
// make misdetection impossible. Reading 32 int64 = 256B is in-bounds even
// for an int32 buffer (E*4 = 6.4MB).
__device__ __forceinline__ bool detect_i64(const void* a, const void* b,
                                           int E, int N) {
    __shared__ int s_i64;
    if (threadIdx.x < 32) {
        int i = threadIdx.x < E ? threadIdx.x : 0;
        long long x = __ldg((const long long*)a + i);
        long long y = __ldg((const long long*)b + i);
        int bad = (x < 0 || x >= (long long)N || y < 0 || y >= (long long)N) ? 1 : 0;
        unsigned m = __ballot_sync(0xFFFFFFFFu, bad);
        if (threadIdx.x == 0) s_i64 = (m == 0u) ? 1 : 0;
    }
    __syncthreads();
    return s_i64 != 0;
}

// ---------------------------------------------------------------------------
__global__ void zero_cnt_kernel(int N) {
    int i = blockIdx.x * blockDim.x + threadIdx.x;
    int st = gridDim.x * blockDim.x;
    for (; i < N; i += st) g_cnt[i] = 0;
}

// ---------------------------------------------------------------------------
__global__ void hist_kernel(const void* __restrict__ srcv,
                            const void* __restrict__ dstv, int E, int N) {
    bool i64 = detect_i64(srcv, dstv, E, N);
    int i = blockIdx.x * blockDim.x + threadIdx.x;
    int st = gridDim.x * blockDim.x;
    if (i64) {
        const long long* d64 = (const long long*)dstv;
        for (; i < E; i += st) atomicAdd(&g_cnt[(int)__ldg(d64 + i)], 1);
    } else {
        const int* d32 = (const int*)dstv;
        for (; i < E; i += st) atomicAdd(&g_cnt[__ldg(d32 + i)], 1);
    }
}

// ---------------------------------------------------------------------------
// Single-block exclusive scan of g_cnt -> g_rowptr / g_cursor.
__global__ void scan_kernel(int N) {
    __shared__ int part[1024];
    int tid = threadIdx.x;
    int chunk = (N + 1023) >> 10;
    int s = tid * chunk;
    int e = s + chunk < N ? s + chunk : N;
    int sum = 0;
    for (int i = s; i < e; i++) sum += g_cnt[i];
    part[tid] = sum;
    __syncthreads();
    for (int off = 1; off < 1024; off <<= 1) {
        int v = (tid >= off) ? part[tid - off] : 0;
        __syncthreads();
        part[tid] += v;
        __syncthreads();
    }
    int run = (tid == 0) ? 0 : part[tid - 1];   // exclusive prefix
    for (int i = s; i < e; i++) {
        g_rowptr[i] = run;
        g_cursor[i] = run;
        run += g_cnt[i];
    }
    if (tid == 1023) g_rowptr[N] = part[1023];  // total = E
}

// ---------------------------------------------------------------------------
__global__ void fill_kernel(const void* __restrict__ srcv,
                            const void* __restrict__ dstv, int E, int N) {
    bool i64 = detect_i64(srcv, dstv, E, N);
    int i = blockIdx.x * blockDim.x + threadIdx.x;
    int st = gridDim.x * blockDim.x;
    if (i64) {
        const long long* s64 = (const long long*)srcv;
        const long long* d64 = (const long long*)dstv;
        for (; i < E; i += st) {
            int d = (int)__ldg(d64 + i);
            int slot = atomicAdd(&g_cursor[d], 1);
            g_colidx[slot] = (int)__ldg(s64 + i);
        }
    } else {
        const int* s32 = (const int*)srcv;
        const int* d32 = (const int*)dstv;
        for (; i < E; i += st) {
            int d = __ldg(d32 + i);
            int slot = atomicAdd(&g_cursor[d], 1);
            g_colidx[slot] = __ldg(s32 + i);
        }
    }
}

// ---------------------------------------------------------------------------
// Pull: one node per 16-lane half-warp, register accumulation (NO atomics).
// Gathers are fully coalesced: 16 lanes read one 256B feat row.
__global__ void pull_kernel(const float* __restrict__ feat, int N) {
    int n = blockIdx.x * 16 + (threadIdx.x >> 4);
    int lane = threadIdx.x & 15;
    unsigned hm = 0xFFFFu << (threadIdx.x & 16);   // own half-warp mask
    if (n >= N) return;
    int e0 = g_rowptr[n], e1 = g_rowptr[n + 1];
    const float4* f4 = (const float4*)feat;
    float4 acc = make_float4(0.f, 0.f, 0.f, 0.f);
    for (int base = e0; base < e1; base += 16) {
        int idx = (base + lane < e1) ? __ldg(g_colidx + base + lane) : 0;
        int cnt = e1 - base < 16 ? e1 - base : 16;
#pragma unroll 4
        for (int j = 0; j < cnt; j++) {
            int s = __shfl_sync(hm, idx, j, 16);
            float4 v = __ldg(f4 + (long long)s * 16 + lane);
            acc.x += v.x; acc.y += v.y; acc.z += v.z; acc.w += v.w;
        }
    }
    float iv = 1.f / fmaxf((float)(e1 - e0), 1.f);
    acc.x *= iv; acc.y *= iv; acc.z *= iv; acc.w *= iv;
    *reinterpret_cast<float4*>(g_hneigh + (long long)n * 64 + lane * 4) = acc;
}

// ---------------------------------------------------------------------------
// Packed f32x2 helpers (Blackwell double-rate fp32 path)
__device__ __forceinline__ unsigned long long pack2(float a, float b) {
    unsigned long long r;
    asm("mov.b64 %0, {%1, %2};" : "=l"(r) : "f"(a), "f"(b));
    return r;
}
__device__ __forceinline__ void unpack2(unsigned long long v, float& a, float& b) {
    asm("mov.b64 {%0, %1}, %2;" : "=f"(a), "=f"(b) : "l"(v));
}
#define FMA2(d, a, b) asm("fma.rn.f32x2 %0, %1, %2, %0;" : "+l"(d) : "l"(a), "l"(b))

// ---------------------------------------------------------------------------
// out = relu(X @ Wc + bias), X[n] = [feat[n] | g_hneigh[n]] (len 128, prescaled)
// Tile: 256 nodes x 64 cols per block (256 threads), 8 nodes x 8 cols/thread.
// k streamed in chunks of 8 (Xs[8][260]); Wc resident (128x64, no pad needed:
// all lanes of a warp read the same k-row, 8 distinct 16B spans = conflict-free).
__global__ __launch_bounds__(256) void out_gemm_kernel(
    const float* __restrict__ feat,
    const float* __restrict__ Ws,
    const float* __restrict__ Wn,
    const float* __restrict__ bias,
    float* __restrict__ out,
    int N) {
    __shared__ float Wc[128][64];   // 32KB
    __shared__ float Xs[8][260];    // 8.3KB; 260*4B row stride is 16B-multiple
    __shared__ float bsh[64];

    int tid = threadIdx.x;
    int nb = blockIdx.x * 256;

    for (int i = tid; i < 64 * 64; i += 256) {
        int k = i >> 6, c = i & 63;
        Wc[k][c] = Ws[i];
        Wc[64 + k][c] = Wn[i];
    }
    if (tid < 64) bsh[tid] = bias[tid];

    const int r0 = (tid >> 3) * 8;   // 32 groups of 8 nodes
    const int c0 = (tid & 7) * 8;    // 8 groups of 8 cols

    unsigned long long acc[8][4];
#pragma unroll
    for (int i = 0; i < 8; i++) {
        acc[i][0] = 0ull; acc[i][1] = 0ull; acc[i][2] = 0ull; acc[i][3] = 0ull;
    }

    // loader: thread tid owns node nb+tid, loads its 8 k-values per chunk
    int gnl = nb + tid;
    if (gnl >= N) gnl = N - 1;       // clamped safe read; store masked later
    const float4* f4 = (const float4*)feat;
    const float4* h4 = (const float4*)g_hneigh;

#pragma unroll 1
    for (int kc = 0; kc < 16; kc++) {
        int kb = kc * 8;
        float4 a, b;
        if (kb < 64) {
            a = __ldg(f4 + (long long)gnl * 16 + (kb >> 2));
            b = __ldg(f4 + (long long)gnl * 16 + (kb >> 2) + 1);
        } else {
            a = __ldg(h4 + (long long)gnl * 16 + ((kb - 64) >> 2));
            b = __ldg(h4 + (long long)gnl * 16 + ((kb - 64) >> 2) + 1);
        }
        __syncthreads();   // previous chunk fully consumed
        Xs[0][tid] = a.x; Xs[1][tid] = a.y; Xs[2][tid] = a.z; Xs[3][tid] = a.w;
        Xs[4][tid] = b.x; Xs[5][tid] = b.y; Xs[6][tid] = b.z; Xs[7][tid] = b.w;
        __syncthreads();

#pragma unroll
        for (int kk = 0; kk < 8; kk++) {
            int k = kb + kk;
            float4 w0 = *reinterpret_cast<const float4*>(&Wc[k][c0]);
            float4 w1 = *reinterpret_cast<const float4*>(&Wc[k][c0 + 4]);
            unsigned long long wp0 = pack2(w0.x, w0.y);
            unsigned long long wp1 = pack2(w0.z, w0.w);
            unsigned long long wp2 = pack2(w1.x, w1.y);
            unsigned long long wp3 = pack2(w1.z, w1.w);
            float4 xa = *reinterpret_cast<const float4*>(&Xs[kk][r0]);
            float4 xb = *reinterpret_cast<const float4*>(&Xs[kk][r0 + 4]);
            float xr[8] = {xa.x, xa.y, xa.z, xa.w, xb.x, xb.y, xb.z, xb.w};
#pragma unroll
            for (int i = 0; i < 8; i++) {
                unsigned long long xx = pack2(xr[i], xr[i]);
                FMA2(acc[i][0], xx, wp0);
                FMA2(acc[i][1], xx, wp1);
                FMA2(acc[i][2], xx, wp2);
                FMA2(acc[i][3], xx, wp3);
            }
        }
    }

    // epilogue: bias + relu + 2x STG.128 per node
    float bb[8];
#pragma unroll
    for (int j = 0; j < 8; j++) bb[j] = bsh[c0 + j];
#pragma unroll
    for (int i = 0; i < 8; i++) {
        int gn = nb + r0 + i;
        if (gn < N) {
            float o[8];
            unpack2(acc[i][0], o[0], o[1]);
            unpack2(acc[i][1], o[2], o[3]);
            unpack2(acc[i][2], o[4], o[5]);
            unpack2(acc[i][3], o[6], o[7]);
            float4 v0, v1;
            v0.x = fmaxf(o[0] + bb[0], 0.f); v0.y = fmaxf(o[1] + bb[1], 0.f);
            v0.z = fmaxf(o[2] + bb[2], 0.f); v0.w = fmaxf(o[3] + bb[3], 0.f);
            v1.x = fmaxf(o[4] + bb[4], 0.f); v1.y = fmaxf(o[5] + bb[5], 0.f);
            v1.z = fmaxf(o[6] + bb[6], 0.f); v1.w = fmaxf(o[7] + bb[7], 0.f);
            float* op = out + (long long)gn * 64 + c0;
            *reinterpret_cast<float4*>(op) = v0;
            *reinterpret_cast<float4*>(op + 4) = v1;
        }
    }
}

// ---------------------------------------------------------------------------
extern "C" void kernel_launch(void* const* d_in, const int* in_sizes, int n_in,
                              void* d_out, int out_size) {
    const float* feat = (const float*)d_in[0];
    const void* src   = d_in[1];
    const void* dst   = d_in[2];
    const float* Ws   = (const float*)d_in[3];
    const float* Wn   = (const float*)d_in[4];
    const float* bias = (const float*)d_in[5];
    float* out = (float*)d_out;

    int N = in_sizes[0] / D_IN;
    int E = in_sizes[1];

    zero_cnt_kernel<<<200, 512>>>(N);
    hist_kernel<<<1024, 256>>>(src, dst, E, N);
    scan_kernel<<<1, 1024>>>(N);
    fill_kernel<<<1024, 256>>>(src, dst, E, N);
    pull_kernel<<<(N + 15) / 16, 256>>>(feat, N);
    out_gemm_kernel<<<(N + 255) / 256, 256>>>(feat, Ws, Wn, bias, out, N);
}